// round 2
// baseline (speedup 1.0000x reference)
#include <cuda_runtime.h>
#include <math.h>

// Problem constants
#define BSZ   2048
#define TT    96
#define DIN   64
#define HH    256
#define KSEG  20     // CRPS knots

// ---------------- device scratch (no allocations allowed) ----------------
__device__ float g_hcat[BSZ * 512];      // [b][0:256]=h0, [b][256:512]=h1
__device__ float g_c0[BSZ * HH];
__device__ float g_c1[BSZ * HH];
__device__ float g_z[BSZ * 1024];        // reused for z0 then z1 each step
__device__ float g_Wcat0[1024 * 320];    // [Wih0 | Whh0]
__device__ float g_Wcat1[1024 * 512];    // [Wih1 | Whh1]
__device__ float g_bias0[1024];
__device__ float g_bias1[1024];
__device__ float g_Wp[21 * 512];         // permuted [W_pb; W_pg] for hcat layout
__device__ float g_pbias[21];

// ---------------- init kernels ----------------
__global__ void zero_state(float* out) {
    int i = blockIdx.x * blockDim.x + threadIdx.x;
    if (i < BSZ * 512) g_hcat[i] = 0.f;
    if (i < BSZ * HH) { g_c0[i] = 0.f; g_c1[i] = 0.f; }
    if (i == 0) out[0] = 0.f;
}

__global__ void build_weights(
    const float* __restrict__ Wih0, const float* __restrict__ Whh0,
    const float* __restrict__ Wih1, const float* __restrict__ Whh1,
    const float* __restrict__ bih0, const float* __restrict__ bhh0,
    const float* __restrict__ bih1, const float* __restrict__ bhh1,
    const float* __restrict__ Wpb,  const float* __restrict__ bpb,
    const float* __restrict__ Wpg,  const float* __restrict__ bpg)
{
    int i = blockIdx.x * blockDim.x + threadIdx.x;
    if (i < 1024 * 320) {
        int n = i / 320, k = i % 320;
        g_Wcat0[i] = (k < 64) ? Wih0[n * 64 + k] : Whh0[n * 256 + (k - 64)];
    }
    if (i < 1024 * 512) {
        int n = i / 512, k = i % 512;
        g_Wcat1[i] = (k < 256) ? Wih1[n * 256 + k] : Whh1[n * 256 + (k - 256)];
    }
    if (i < 21 * 512) {
        int m = i / 512, k = i % 512;
        // hp[2j+l] = hcat[j + 256*l]  =>  Wp[m][j+256l] = W[m][2j+l]
        int src = 2 * (k & 255) + (k >> 8);
        g_Wp[i] = (m == 0) ? Wpb[src] : Wpg[(m - 1) * 512 + src];
    }
    if (i < 1024) { g_bias0[i] = bih0[i] + bhh0[i]; g_bias1[i] = bih1[i] + bhh1[i]; }
    if (i < 21)   { g_pbias[i] = (i == 0) ? bpb[0] : bpg[i - 1]; }
}

// ---------------- GEMM: Z = A @ W^T + bias ----------------
// MODE 0: A = [x_t (K=64, stride 6144) | hcat[:,0:256]],  W=g_Wcat0, K=320
// MODE 1: A = hcat (K=512),                               W=g_Wcat1, K=512
#define BM 128
#define BN 128
#define BK 16
#define TM 8
#define TN 8

template <int MODE>
__global__ __launch_bounds__(256, 2)
void gemm_lstm(const float* __restrict__ xt)   // xt = train + t*64 (MODE 0 only)
{
    constexpr int K = (MODE == 0) ? 320 : 512;
    const float* __restrict__ W    = (MODE == 0) ? g_Wcat0 : g_Wcat1;
    const float* __restrict__ bias = (MODE == 0) ? g_bias0 : g_bias1;

    __shared__ float As[BK][BM + 4];
    __shared__ float Bs[BK][BN + 4];

    const int tid  = threadIdx.x;
    const int row0 = blockIdx.y * BM;
    const int col0 = blockIdx.x * BN;

    const int a_m = tid >> 1;
    const int a_k = (tid & 1) * 8;
    const int b_n = tid >> 1;
    const int b_k = (tid & 1) * 8;

    const int tx = tid & 15;
    const int ty = tid >> 4;

    float acc[TM][TN];
#pragma unroll
    for (int r = 0; r < TM; r++)
#pragma unroll
        for (int c = 0; c < TN; c++) acc[r][c] = 0.f;

#pragma unroll 1
    for (int k0 = 0; k0 < K; k0 += BK) {
        // ---- load A tile ----
        const float* Abase;
        int lda, kloc;
        if (MODE == 0 && k0 < 64) { Abase = xt;     lda = TT * DIN; kloc = k0; }
        else if (MODE == 0)       { Abase = g_hcat; lda = 512;      kloc = k0 - 64; }
        else                      { Abase = g_hcat; lda = 512;      kloc = k0; }
#pragma unroll
        for (int i = 0; i < 2; i++) {
            float4 v = *(const float4*)(Abase + (size_t)(row0 + a_m) * lda + kloc + a_k + i * 4);
            As[a_k + i * 4 + 0][a_m] = v.x;
            As[a_k + i * 4 + 1][a_m] = v.y;
            As[a_k + i * 4 + 2][a_m] = v.z;
            As[a_k + i * 4 + 3][a_m] = v.w;
        }
        // ---- load W tile (W is [1024][K], K contiguous) ----
#pragma unroll
        for (int i = 0; i < 2; i++) {
            float4 v = *(const float4*)(W + (size_t)(col0 + b_n) * K + k0 + b_k + i * 4);
            Bs[b_k + i * 4 + 0][b_n] = v.x;
            Bs[b_k + i * 4 + 1][b_n] = v.y;
            Bs[b_k + i * 4 + 2][b_n] = v.z;
            Bs[b_k + i * 4 + 3][b_n] = v.w;
        }
        __syncthreads();

#pragma unroll
        for (int k = 0; k < BK; k++) {
            float4 a0 = *(const float4*)&As[k][ty * TM];
            float4 a1 = *(const float4*)&As[k][ty * TM + 4];
            float4 b0 = *(const float4*)&Bs[k][tx * TN];
            float4 b1 = *(const float4*)&Bs[k][tx * TN + 4];
            float ra[TM] = {a0.x, a0.y, a0.z, a0.w, a1.x, a1.y, a1.z, a1.w};
            float rb[TN] = {b0.x, b0.y, b0.z, b0.w, b1.x, b1.y, b1.z, b1.w};
#pragma unroll
            for (int r = 0; r < TM; r++)
#pragma unroll
                for (int c = 0; c < TN; c++) acc[r][c] += ra[r] * rb[c];
        }
        __syncthreads();
    }

    // ---- epilogue: add bias, write Z ----
#pragma unroll
    for (int r = 0; r < TM; r++) {
        int m = row0 + ty * TM + r;
        float* zrow = g_z + (size_t)m * 1024;
#pragma unroll
        for (int c = 0; c < TN; c += 4) {
            int n = col0 + tx * TN + c;
            float4 v;
            v.x = acc[r][c + 0] + bias[n + 0];
            v.y = acc[r][c + 1] + bias[n + 1];
            v.z = acc[r][c + 2] + bias[n + 2];
            v.w = acc[r][c + 3] + bias[n + 3];
            *(float4*)(zrow + n) = v;
        }
    }
}

// ---------------- LSTM elementwise ----------------
template <int LAYER>
__global__ void lstm_act()
{
    int idx = blockIdx.x * blockDim.x + threadIdx.x;
    if (idx >= BSZ * HH) return;
    int b = idx >> 8, h = idx & 255;
    const float* z = g_z + (size_t)b * 1024;
    float zi = z[h], zf = z[HH + h], zg = z[2 * HH + h], zo = z[3 * HH + h];
    float ig = 1.f / (1.f + expf(-zi));
    float fg = 1.f / (1.f + expf(-zf));
    float og = 1.f / (1.f + expf(-zo));
    float* c = (LAYER == 0) ? g_c0 : g_c1;
    float c2 = fg * c[idx] + ig * tanhf(zg);
    c[idx] = c2;
    g_hcat[b * 512 + (LAYER == 0 ? 0 : 256) + h] = og * tanhf(c2);
}

// ---------------- projection + softplus + CRPS ----------------
__device__ __forceinline__ float softplusf(float x) {
    return fmaxf(x, 0.f) + log1pf(expf(-fabsf(x)));
}

__global__ void proj_crps(const float* __restrict__ labels, int t,
                          float* __restrict__ out)
{
    int b = blockIdx.x;
    int lane = threadIdx.x;

    float hreg[16];
    const float* hrow = g_hcat + (size_t)b * 512;
#pragma unroll
    for (int j = 0; j < 16; j++) hreg[j] = hrow[lane + 32 * j];

    __shared__ float sp[21];
    for (int m = 0; m < 21; m++) {
        const float* w = g_Wp + m * 512;
        float a = 0.f;
#pragma unroll
        for (int j = 0; j < 16; j++) a += hreg[j] * w[lane + 32 * j];
#pragma unroll
        for (int o = 16; o; o >>= 1) a += __shfl_xor_sync(0xFFFFFFFFu, a, o);
        if (lane == 0) sp[m] = softplusf(a + g_pbias[m]);
    }
    __syncwarp();

    if (lane == 0) {
        const float invk = 1.0f / (float)KSEG;
        float beta0 = sp[0];
        float g[KSEG];
#pragma unroll
        for (int j = 0; j < KSEG; j++) g[j] = sp[1 + j];

        float braw[KSEG];
        braw[0] = (g[0] - beta0) * (0.5f * KSEG);
#pragma unroll
        for (int i = 1; i < KSEG; i++) braw[i] = (g[i] - g[i - 1]) * (0.5f * KSEG);
        float bb[KSEG];
        bb[0] = braw[0];
#pragma unroll
        for (int i = 1; i < KSEG; i++) bb[i] = braw[i] - braw[i - 1];
        float ssum = 0.f;
#pragma unroll
        for (int i = 0; i < KSEG - 1; i++) ssum += bb[i];
        bb[KSEG - 1] = g[KSEG - 1] - ssum;

        // F at interior knots
        float F[KSEG];
        for (int i = 0; i < KSEG; i++) {
            float acc = (float)(i + 1) * invk * beta0;
            for (int j = 0; j <= i; j++) {
                float d = (float)(i + 1 - j) * invk;
                acc += d * d * bb[j];
            }
            F[i] = acc;
        }

        float y = labels[b * TT + t];
        float A = 0.f, Bc = beta0, C = -y;
        float mind = 1e30f; int amin = 0;
        unsigned almask = 0;
        for (int i = 0; i < KSEG; i++) {
            float knot = (i == 0) ? 0.f : F[i - 1];
            float diff = y - knot;
            float ad = fabsf(diff);
            if (ad < mind) { mind = ad; amin = i; }
            if (diff > 0.f) {
                almask |= (1u << i);
                float ksi = (float)i * invk;
                A += bb[i];
                Bc -= 2.f * bb[i] * ksi;
                C += bb[i] * ksi * ksi;
            }
        }
        float disc = Bc * Bc - 4.f * A * C;
        float alpha;
        if (A != 0.f && disc >= 0.f)       alpha = (-Bc + sqrtf(disc)) / (2.f * A);
        else if (A == 0.f)                 alpha = -C / ((Bc == 0.f) ? 1.f : Bc);
        else                               alpha = (float)amin * invk;

        float crps = -y * (1.f - 2.f * alpha) + beta0 * (1.f / 3.f - alpha * alpha);
        for (int i = 0; i < KSEG; i++) {
            float ksi = (float)i * invk;
            float om = 1.f - ksi;
            crps += bb[i] * (1.f / 6.f) * om * om * om * om;
            if ((almask >> i) & 1u) {
                float d = alpha - ksi;
                crps -= (2.f / 3.f) * bb[i] * d * d * d;
            }
        }
        atomicAdd(out, crps * (1.0f / (float)BSZ));
    }
}

// ---------------- host launch ----------------
extern "C" void kernel_launch(void* const* d_in, const int* in_sizes, int n_in,
                              void* d_out, int out_size)
{
    const float* train  = (const float*)d_in[0];
    const float* labels = (const float*)d_in[1];
    const float* Wih0 = (const float*)d_in[2];
    const float* Whh0 = (const float*)d_in[3];
    const float* Wih1 = (const float*)d_in[4];
    const float* Whh1 = (const float*)d_in[5];
    const float* bih0 = (const float*)d_in[6];
    const float* bhh0 = (const float*)d_in[7];
    const float* bih1 = (const float*)d_in[8];
    const float* bhh1 = (const float*)d_in[9];
    const float* Wpb  = (const float*)d_in[10];
    const float* bpb  = (const float*)d_in[11];
    const float* Wpg  = (const float*)d_in[12];
    const float* bpg  = (const float*)d_in[13];
    float* out = (float*)d_out;

    zero_state<<<(BSZ * 512 + 255) / 256, 256>>>(out);
    build_weights<<<(1024 * 512 + 255) / 256, 256>>>(
        Wih0, Whh0, Wih1, Whh1, bih0, bhh0, bih1, bhh1, Wpb, bpb, Wpg, bpg);

    dim3 gemm_grid(1024 / BN, BSZ / BM);   // (8, 16)
    for (int t = 0; t < TT; t++) {
        gemm_lstm<0><<<gemm_grid, 256>>>(train + (size_t)t * DIN);
        lstm_act<0><<<(BSZ * HH + 255) / 256, 256>>>();
        gemm_lstm<1><<<gemm_grid, 256>>>(nullptr);
        lstm_act<1><<<(BSZ * HH + 255) / 256, 256>>>();
        proj_crps<<<BSZ, 32>>>(labels, t, out);
    }
}